// round 3
// baseline (speedup 1.0000x reference)
#include <cuda_runtime.h>
#include <cuda_bf16.h>
#include <stdint.h>

#define N_NODES_MAX 50048
#define FEAT 128

__device__ __align__(256) float g_deg[N_NODES_MAX];
__device__ __align__(256) float g_agg[N_NODES_MAX * FEAT];
__device__ __align__(256) float g_h0[N_NODES_MAX * FEAT];
__device__ __align__(256) float g_h1[N_NODES_MAX * FEAT];
__device__ int g_is64;   // 1 if edge_index is int64, 0 if int32

// ---------------------------------------------------------------------------
// dtype detection: int64 edge data => high 32-bit word of every element is 0.
// Sample 64 odd words; if all zero -> int64.
// ---------------------------------------------------------------------------
__global__ void detect_kernel(const int* __restrict__ ei_w, int nwords, int* __restrict__ flag) {
    if (threadIdx.x == 0 && blockIdx.x == 0) {
        int all_zero = 1;
        for (int i = 0; i < 64; i++) {
            int pos = 1 + 2 * i;           // odd words
            if (pos < nwords && ei_w[pos] != 0) { all_zero = 0; break; }
        }
        *flag = all_zero;
    }
}

__device__ __forceinline__ int edge_idx(const void* ei, long long pos, int is64) {
    if (is64) return (int)((const long long*)ei)[pos];
    return ((const int*)ei)[pos];
}

// ---------------------------------------------------------------------------
// degree: one thread per edge
// ---------------------------------------------------------------------------
__global__ void degree_kernel(const void* __restrict__ ei, float* __restrict__ deg,
                              int E, int M, const int* __restrict__ flag) {
    int e = blockIdx.x * blockDim.x + threadIdx.x;
    if (e >= E) return;
    int is64 = *flag;
    int d = edge_idx(ei, (long long)E + e, is64);
    if (d < 0 || d >= M) return;
    atomicAdd(&deg[d], 1.0f);
}

__global__ void deginv_kernel(float* __restrict__ deg, int M) {
    int i = blockIdx.x * blockDim.x + threadIdx.x;
    if (i >= M) return;
    deg[i] = 1.0f / fmaxf(deg[i], 1.0f);
}

// ---------------------------------------------------------------------------
// scatter-add: one warp per edge; lane i handles 4 floats via vectorized red
// ---------------------------------------------------------------------------
__global__ void scatter_kernel(const float* __restrict__ feat,
                               const void* __restrict__ ei,
                               float* __restrict__ agg, int E, int M,
                               const int* __restrict__ flag) {
    int warp = (blockIdx.x * blockDim.x + threadIdx.x) >> 5;
    int lane = threadIdx.x & 31;
    if (warp >= E) return;
    int is64 = *flag;
    int s = edge_idx(ei, warp, is64);
    int d = edge_idx(ei, (long long)E + warp, is64);
    if (s < 0 || s >= M || d < 0 || d >= M) return;
    float4 v = *((const float4*)(feat + (size_t)s * FEAT) + lane);
    float* dst = agg + (size_t)d * FEAT + lane * 4;
    asm volatile("red.global.add.v4.f32 [%0], {%1,%2,%3,%4};"
                 :: "l"(dst), "f"(v.x), "f"(v.y), "f"(v.z), "f"(v.w)
                 : "memory");
}

// ---------------------------------------------------------------------------
// Fused GEMM:
//   HAS_AGG: out = act( (Aagg * dinv[row]) @ Wl + Xr @ Wr + bias )
//   else:    out = Xr @ Wr + bias
// ---------------------------------------------------------------------------
#define TM 64
#define TK 16
#define APAD 68

template<int N, bool HAS_AGG, bool RELU>
__global__ void __launch_bounds__(256)
fused_gemm(const float* __restrict__ Aagg, const float* __restrict__ dinv,
           const float* __restrict__ Xr,
           const float* __restrict__ Wl, const float* __restrict__ Wr,
           const float* __restrict__ bias,
           float* __restrict__ out, int M) {
    __shared__ __align__(16) float As[TK][APAD];
    __shared__ __align__(16) float Bs[TK][N];

    const int m0 = blockIdx.x * TM;
    const int tx = threadIdx.x & 31;
    const int ty = threadIdx.x >> 5;
    constexpr int JC = N / 32;

    float acc[8][JC];
#pragma unroll
    for (int i = 0; i < 8; i++)
#pragma unroll
        for (int j = 0; j < JC; j++) acc[i][j] = 0.0f;

    const int nOps = HAS_AGG ? 2 : 1;
    for (int op = 0; op < nOps; op++) {
        const float* A = (HAS_AGG && op == 0) ? Aagg : Xr;
        const float* B = (HAS_AGG && op == 0) ? Wl : Wr;

        for (int k0 = 0; k0 < FEAT; k0 += TK) {
            {
                int r  = threadIdx.x >> 2;
                int kb = (threadIdx.x & 3) * 4;
                int gr = m0 + r;
                float4 av = make_float4(0.f, 0.f, 0.f, 0.f);
                if (gr < M) {
                    av = *(const float4*)(A + (size_t)gr * FEAT + k0 + kb);
                    if (HAS_AGG && op == 0) {
                        float sc = dinv[gr];
                        av.x *= sc; av.y *= sc; av.z *= sc; av.w *= sc;
                    }
                }
                As[kb + 0][r] = av.x;
                As[kb + 1][r] = av.y;
                As[kb + 2][r] = av.z;
                As[kb + 3][r] = av.w;
            }
#pragma unroll
            for (int i = 0; i < (TK * N) / 256; i++) {
                int idx = threadIdx.x + 256 * i;
                int kk  = idx / N;
                int col = idx % N;
                Bs[kk][col] = B[(size_t)(k0 + kk) * N + col];
            }
            __syncthreads();

#pragma unroll
            for (int kk = 0; kk < TK; kk++) {
                float4 a0 = *(const float4*)&As[kk][ty * 8];
                float4 a1 = *(const float4*)&As[kk][ty * 8 + 4];
                float a[8] = {a0.x, a0.y, a0.z, a0.w, a1.x, a1.y, a1.z, a1.w};
                float b[JC];
#pragma unroll
                for (int jc = 0; jc < JC; jc++) b[jc] = Bs[kk][tx + 32 * jc];
#pragma unroll
                for (int ir = 0; ir < 8; ir++)
#pragma unroll
                    for (int jc = 0; jc < JC; jc++)
                        acc[ir][jc] = fmaf(a[ir], b[jc], acc[ir][jc]);
            }
            __syncthreads();
        }
    }

#pragma unroll
    for (int ir = 0; ir < 8; ir++) {
        int gr = m0 + ty * 8 + ir;
        if (gr >= M) continue;
#pragma unroll
        for (int jc = 0; jc < JC; jc++) {
            int c = tx + 32 * jc;
            float v = acc[ir][jc] + bias[c];
            if (RELU) v = fmaxf(v, 0.0f);
            out[(size_t)gr * N + c] = v;
        }
    }
}

// ---------------------------------------------------------------------------
extern "C" void kernel_launch(void* const* d_in, const int* in_sizes, int n_in,
                              void* d_out, int out_size) {
    const float* x   = (const float*)d_in[0];
    const void*  ei  = d_in[1];
    const float* Wl0 = (const float*)d_in[2];
    const float* Wr0 = (const float*)d_in[3];
    const float* b0  = (const float*)d_in[4];
    const float* Wl1 = (const float*)d_in[5];
    const float* Wr1 = (const float*)d_in[6];
    const float* b1  = (const float*)d_in[7];
    const float* Wfc = (const float*)d_in[8];
    const float* bfc = (const float*)d_in[9];
    float*       out = (float*)d_out;

    const int M = in_sizes[0] / FEAT;   // 50000
    const int E = in_sizes[1] / 2;      // 800000

    float *deg, *agg, *h0, *h1;
    int* flag;
    cudaGetSymbolAddress((void**)&deg, g_deg);
    cudaGetSymbolAddress((void**)&agg, g_agg);
    cudaGetSymbolAddress((void**)&h0,  g_h0);
    cudaGetSymbolAddress((void**)&h1,  g_h1);
    cudaGetSymbolAddress((void**)&flag, g_is64);

    cudaMemsetAsync(deg, 0, (size_t)M * sizeof(float));
    cudaMemsetAsync(agg, 0, (size_t)M * FEAT * sizeof(float));

    // Detect whether edge_index is int32 or int64 (JAX downcasts int64->int32
    // when x64 mode is off, so metadata may differ from the reference source).
    detect_kernel<<<1, 32>>>((const int*)ei, 2 * E, flag);

    degree_kernel<<<(E + 255) / 256, 256>>>(ei, deg, E, M, flag);
    deginv_kernel<<<(M + 255) / 256, 256>>>(deg, M);

    const int scatterBlocks = (E * 32 + 255) / 256;
    const int gemmBlocks    = (M + TM - 1) / TM;

    // layer 0
    scatter_kernel<<<scatterBlocks, 256>>>(x, ei, agg, E, M, flag);
    fused_gemm<128, true, true><<<gemmBlocks, 256>>>(agg, deg, x, Wl0, Wr0, b0, h0, M);

    // layer 1
    cudaMemsetAsync(agg, 0, (size_t)M * FEAT * sizeof(float));
    scatter_kernel<<<scatterBlocks, 256>>>(h0, ei, agg, E, M, flag);
    fused_gemm<128, true, true><<<gemmBlocks, 256>>>(agg, deg, h0, Wl1, Wr1, b1, h1, M);

    // fc
    fused_gemm<64, false, false><<<gemmBlocks, 256>>>(nullptr, nullptr, h1, nullptr, Wfc, bfc, out, M);
}

// round 5
// speedup vs baseline: 1.5495x; 1.5495x over previous
#include <cuda_runtime.h>
#include <cuda_bf16.h>
#include <stdint.h>

#define N_NODES_MAX 50048
#define FEAT 128

__device__ __align__(256) float g_deg[N_NODES_MAX];
__device__ __align__(256) float g_agg[N_NODES_MAX * FEAT];
__device__ __align__(256) float g_h0[N_NODES_MAX * FEAT];
__device__ __align__(256) float g_h1[N_NODES_MAX * FEAT];
__device__ int g_is64;

// bf16 weight blobs, plain [n][k] row-major (k fastest, 128 k per row):
// [Wl0, Wr0, Wl1, Wr1, Wfc][hi/lo]
__device__ __align__(256) unsigned char g_wb[5][2][32768];

// ===========================================================================
// helpers
// ===========================================================================
__device__ __forceinline__ uint32_t smem_u32(const void* p) {
    uint32_t a;
    asm("{ .reg .u64 t; cvta.to.shared.u64 t, %1; cvt.u32.u64 %0, t; }" : "=r"(a) : "l"(p));
    return a;
}
__device__ __forceinline__ uint32_t pack_bf16x2(float x, float y) {
    __nv_bfloat162 v(__float2bfloat16(x), __float2bfloat16(y));
    return *(uint32_t*)&v;
}
__device__ __forceinline__ void ldmatrix_x4(uint32_t* r, uint32_t addr) {
    asm volatile("ldmatrix.sync.aligned.m8n8.x4.shared.b16 {%0,%1,%2,%3}, [%4];"
                 : "=r"(r[0]), "=r"(r[1]), "=r"(r[2]), "=r"(r[3]) : "r"(addr));
}
__device__ __forceinline__ void mma16816(float* d, const uint32_t* a, uint32_t b0, uint32_t b1) {
    asm volatile("mma.sync.aligned.m16n8k16.row.col.f32.bf16.bf16.f32 "
                 "{%0,%1,%2,%3}, {%4,%5,%6,%7}, {%8,%9}, {%0,%1,%2,%3};"
                 : "+f"(d[0]), "+f"(d[1]), "+f"(d[2]), "+f"(d[3])
                 : "r"(a[0]), "r"(a[1]), "r"(a[2]), "r"(a[3]), "r"(b0), "r"(b1));
}

// ===========================================================================
// edge dtype detection + graph kernels
// ===========================================================================
__global__ void detect_kernel(const int* __restrict__ ei_w, int nwords, int* __restrict__ flag) {
    if (threadIdx.x == 0 && blockIdx.x == 0) {
        int all_zero = 1;
        for (int i = 0; i < 64; i++) {
            int pos = 1 + 2 * i;
            if (pos < nwords && ei_w[pos] != 0) { all_zero = 0; break; }
        }
        *flag = all_zero;
    }
}

__device__ __forceinline__ int edge_idx(const void* ei, long long pos, int is64) {
    if (is64) return (int)((const long long*)ei)[pos];
    return ((const int*)ei)[pos];
}

__global__ void degree_kernel(const void* __restrict__ ei, float* __restrict__ deg,
                              int E, int M, const int* __restrict__ flag) {
    int e = blockIdx.x * blockDim.x + threadIdx.x;
    if (e >= E) return;
    int d = edge_idx(ei, (long long)E + e, *flag);
    if (d < 0 || d >= M) return;
    atomicAdd(&deg[d], 1.0f);
}

__global__ void deginv_kernel(float* __restrict__ deg, int M) {
    int i = blockIdx.x * blockDim.x + threadIdx.x;
    if (i >= M) return;
    deg[i] = 1.0f / fmaxf(deg[i], 1.0f);
}

// scatter: 4 edges per warp, loads batched before REDGs for MLP=4
__global__ void scatter_kernel(const float* __restrict__ feat,
                               const void* __restrict__ ei,
                               float* __restrict__ agg, int E, int M,
                               const int* __restrict__ flag) {
    int warp = (blockIdx.x * blockDim.x + threadIdx.x) >> 5;
    int lane = threadIdx.x & 31;
    long long e0 = (long long)warp * 4;
    if (e0 >= E) return;
    int is64 = *flag;
    float4 v[4];
    int d[4];
#pragma unroll
    for (int j = 0; j < 4; j++) {
        d[j] = -1;
        if (e0 + j < E) {
            int s = edge_idx(ei, e0 + j, is64);
            int dd = edge_idx(ei, (long long)E + e0 + j, is64);
            if (s >= 0 && s < M && dd >= 0 && dd < M) {
                v[j] = *((const float4*)(feat + (size_t)s * FEAT) + lane);
                d[j] = dd;
            }
        }
    }
#pragma unroll
    for (int j = 0; j < 4; j++) {
        if (d[j] >= 0) {
            float* dst = agg + (size_t)d[j] * FEAT + lane * 4;
            asm volatile("red.global.add.v4.f32 [%0], {%1,%2,%3,%4};"
                         :: "l"(dst), "f"(v[j].x), "f"(v[j].y), "f"(v[j].z), "f"(v[j].w)
                         : "memory");
        }
    }
}

// ===========================================================================
// weight prep: transpose + hi/lo bf16 split. Blob layout: [n][k], k fastest.
// W input is [K=128, N] row-major f32.
// ===========================================================================
__global__ void prep_w(const float* __restrict__ W, int N,
                       unsigned char* __restrict__ bh, unsigned char* __restrict__ bl) {
    int idx = blockIdx.x * blockDim.x + threadIdx.x;
    if (idx >= N * 128) return;
    int n = idx >> 7, k = idx & 127;
    float w = W[k * N + n];
    __nv_bfloat16 h = __float2bfloat16(w);
    __nv_bfloat16 l = __float2bfloat16(w - __bfloat162float(h));
    *(__nv_bfloat16*)(bh + n * 256 + k * 2) = h;
    *(__nv_bfloat16*)(bl + n * 256 + k * 2) = l;
}

// ===========================================================================
// HMMA GEMM: out = act( sum_ops A_op @ W_op^T + bias ), W blobs are [n][k].
// CTA tile: 128 rows x N cols, 256 threads (8 warps, 4x2 warp grid).
// Hi/lo split: 3 passes (Ah*Bh, Al*Bh, Ah*Bl) accumulated in f32 frags.
// SMEM rows padded to 272 B (128 bf16 + 16 B) -> conflict-free ldmatrix.
// ===========================================================================
#define ROWB 272

template<int N, int NOPS, bool SCALE0, bool RELU>
__global__ void __launch_bounds__(256)
sage_gemm(const float* __restrict__ A0, const float* __restrict__ dinv,
          const float* __restrict__ A1,
          const unsigned char* __restrict__ B0h, const unsigned char* __restrict__ B0l,
          const unsigned char* __restrict__ B1h, const unsigned char* __restrict__ B1l,
          const float* __restrict__ bias, float* __restrict__ out, int M) {
    extern __shared__ __align__(16) unsigned char smem[];
    constexpr int SM_AH = 0;
    constexpr int SM_AL = 128 * ROWB;
    constexpr int SM_BH = 2 * 128 * ROWB;
    constexpr int SM_BL = SM_BH + N * ROWB;
    constexpr int NP = N / 32;          // ldmatrix-x4 B pairs per warp (warp covers N/2 cols)
    constexpr int NJ = 2 * NP;          // n8 blocks per warp

    const int tid  = threadIdx.x;
    const int wid  = tid >> 5;
    const int lane = tid & 31;
    const int mw   = wid >> 1;          // 0..3
    const int nw   = wid & 1;           // 0..1
    const int mbase = mw * 32;
    const int nbase = nw * (N / 2);
    const int m0 = blockIdx.x * 128;
    const uint32_t sb = smem_u32(smem);

    float acc[2][NJ][4];
#pragma unroll
    for (int t = 0; t < 2; t++)
#pragma unroll
        for (int j = 0; j < NJ; j++)
#pragma unroll
            for (int q = 0; q < 4; q++) acc[t][j][q] = 0.0f;

    // per-thread ldmatrix source addresses (fixed across k via +32B steps)
    const uint32_t aAddrBase = sb + SM_AH + (uint32_t)(mbase + (lane & 15)) * ROWB
                             + ((lane >> 4) & 1) * 16;
    const uint32_t bRow = (uint32_t)(nbase + (lane & 7) + ((lane >> 4) & 1) * 8);
    const uint32_t bAddrBase = sb + SM_BH + bRow * ROWB + ((lane >> 3) & 1) * 16;

    for (int op = 0; op < NOPS; op++) {
        const float* A = (op == 0) ? A0 : A1;
        const unsigned char* Bh = (op == 0) ? B0h : B1h;
        const unsigned char* Bl = (op == 0) ? B0l : B1l;

        if (op > 0) __syncthreads();    // protect smem reuse

        // --- A tile: f32 -> hi/lo bf16, padded rows ---
#pragma unroll
        for (int i = 0; i < 16; i++) {
            int g = tid + 256 * i;       // 4096 float4 groups
            int r = g >> 5;
            int kb = (g & 31) << 2;
            int gr = m0 + r;
            float4 a = make_float4(0.f, 0.f, 0.f, 0.f);
            if (gr < M) {
                a = *(const float4*)(A + (size_t)gr * FEAT + kb);
                if (SCALE0 && op == 0) {
                    float sc = dinv[gr];
                    a.x *= sc; a.y *= sc; a.z *= sc; a.w *= sc;
                }
            }
            __nv_bfloat16 hx = __float2bfloat16(a.x), hy = __float2bfloat16(a.y);
            __nv_bfloat16 hz = __float2bfloat16(a.z), hw = __float2bfloat16(a.w);
            uint2 hv, lv;
            {
                __nv_bfloat162 p0(hx, hy), p1(hz, hw);
                hv.x = *(uint32_t*)&p0; hv.y = *(uint32_t*)&p1;
            }
            lv.x = pack_bf16x2(a.x - __bfloat162float(hx), a.y - __bfloat162float(hy));
            lv.y = pack_bf16x2(a.z - __bfloat162float(hz), a.w - __bfloat162float(hw));
            uint32_t off = (uint32_t)r * ROWB + kb * 2;
            *(uint2*)(smem + SM_AH + off) = hv;
            *(uint2*)(smem + SM_AL + off) = lv;
        }
        // --- B tiles: copy blob rows (256 B) into padded rows ---
#pragma unroll
        for (int i = 0; i < (N * 16) / 256; i++) {
            int g = tid + 256 * i;
            int row = g >> 4, col = g & 15;
            uint32_t off = (uint32_t)row * ROWB + col * 16;
            *(uint4*)(smem + SM_BH + off) = ((const uint4*)Bh)[g];
            *(uint4*)(smem + SM_BL + off) = ((const uint4*)Bl)[g];
        }
        __syncthreads();

        // --- 3 passes ---
#pragma unroll
        for (int pass = 0; pass < 3; pass++) {
            uint32_t aBase = aAddrBase + ((pass == 1) ? (uint32_t)(SM_AL - SM_AH) : 0u);
            uint32_t bBase = bAddrBase + ((pass == 2) ? (uint32_t)(SM_BL - SM_BH) : 0u);
#pragma unroll
            for (int ks = 0; ks < 8; ks++) {
                uint32_t kOff = ks * 32;
                uint32_t af[2][4];
                ldmatrix_x4(af[0], aBase + kOff);
                ldmatrix_x4(af[1], aBase + 16 * ROWB + kOff);
                uint32_t bf[NP][4];
#pragma unroll
                for (int p = 0; p < NP; p++)
                    ldmatrix_x4(bf[p], bBase + (uint32_t)(p * 16) * ROWB + kOff);
#pragma unroll
                for (int t = 0; t < 2; t++)
#pragma unroll
                    for (int p = 0; p < NP; p++) {
                        mma16816(acc[t][2 * p + 0], af[t], bf[p][0], bf[p][1]);
                        mma16816(acc[t][2 * p + 1], af[t], bf[p][2], bf[p][3]);
                    }
            }
        }
    }

    // --- epilogue ---
    const int group = lane >> 2;
    const int tig   = lane & 3;
#pragma unroll
    for (int t = 0; t < 2; t++) {
#pragma unroll
        for (int j = 0; j < NJ; j++) {
            int col = nbase + j * 8 + tig * 2;
            float2 b = *(const float2*)(bias + col);
            int r0 = m0 + mbase + t * 16 + group;
            float2 o0, o1;
            o0.x = acc[t][j][0] + b.x; o0.y = acc[t][j][1] + b.y;
            o1.x = acc[t][j][2] + b.x; o1.y = acc[t][j][3] + b.y;
            if (RELU) {
                o0.x = fmaxf(o0.x, 0.f); o0.y = fmaxf(o0.y, 0.f);
                o1.x = fmaxf(o1.x, 0.f); o1.y = fmaxf(o1.y, 0.f);
            }
            if (r0 < M)     *(float2*)(out + (size_t)r0 * N + col)       = o0;
            if (r0 + 8 < M) *(float2*)(out + (size_t)(r0 + 8) * N + col) = o1;
        }
    }
}

// ===========================================================================
extern "C" void kernel_launch(void* const* d_in, const int* in_sizes, int n_in,
                              void* d_out, int out_size) {
    const float* x   = (const float*)d_in[0];
    const void*  ei  = d_in[1];
    const float* Wl0 = (const float*)d_in[2];
    const float* Wr0 = (const float*)d_in[3];
    const float* b0  = (const float*)d_in[4];
    const float* Wl1 = (const float*)d_in[5];
    const float* Wr1 = (const float*)d_in[6];
    const float* b1  = (const float*)d_in[7];
    const float* Wfc = (const float*)d_in[8];
    const float* bfc = (const float*)d_in[9];
    float*       out = (float*)d_out;

    const int M = in_sizes[0] / FEAT;   // 50000
    const int E = in_sizes[1] / 2;      // 800000

    float *deg, *agg, *h0, *h1;
    int* flag;
    unsigned char* wb;
    cudaGetSymbolAddress((void**)&deg, g_deg);
    cudaGetSymbolAddress((void**)&agg, g_agg);
    cudaGetSymbolAddress((void**)&h0,  g_h0);
    cudaGetSymbolAddress((void**)&h1,  g_h1);
    cudaGetSymbolAddress((void**)&flag, g_is64);
    cudaGetSymbolAddress((void**)&wb, g_wb);
    auto blob = [&](int w, int hl) { return wb + ((size_t)w * 2 + hl) * 32768; };

    const int smemL = (2 * 128 + 2 * 128) * ROWB;   // 139264
    const int smemF = (2 * 128 + 2 * 64) * ROWB;    // 104448
    cudaFuncSetAttribute(sage_gemm<128, 2, true, true>,  cudaFuncAttributeMaxDynamicSharedMemorySize, smemL);
    cudaFuncSetAttribute(sage_gemm<64, 1, false, false>, cudaFuncAttributeMaxDynamicSharedMemorySize, smemF);

    cudaMemsetAsync(deg, 0, (size_t)M * sizeof(float));
    cudaMemsetAsync(agg, 0, (size_t)M * FEAT * sizeof(float));

    detect_kernel<<<1, 32>>>((const int*)ei, 2 * E, flag);

    prep_w<<<64, 256>>>(Wl0, 128, blob(0, 0), blob(0, 1));
    prep_w<<<64, 256>>>(Wr0, 128, blob(1, 0), blob(1, 1));
    prep_w<<<64, 256>>>(Wl1, 128, blob(2, 0), blob(2, 1));
    prep_w<<<64, 256>>>(Wr1, 128, blob(3, 0), blob(3, 1));
    prep_w<<<32, 256>>>(Wfc, 64,  blob(4, 0), blob(4, 1));

    degree_kernel<<<(E + 255) / 256, 256>>>(ei, deg, E, M, flag);
    deginv_kernel<<<(M + 255) / 256, 256>>>(deg, M);

    const int scatterBlocks = ((E + 3) / 4 * 32 + 255) / 256;
    const int gemmBlocks    = (M + 127) / 128;

    // layer 0
    scatter_kernel<<<scatterBlocks, 256>>>(x, ei, agg, E, M, flag);
    sage_gemm<128, 2, true, true><<<gemmBlocks, 256, smemL>>>(
        agg, deg, x, blob(0, 0), blob(0, 1), blob(1, 0), blob(1, 1), b0, h0, M);

    // layer 1
    cudaMemsetAsync(agg, 0, (size_t)M * FEAT * sizeof(float));
    scatter_kernel<<<scatterBlocks, 256>>>(h0, ei, agg, E, M, flag);
    sage_gemm<128, 2, true, true><<<gemmBlocks, 256, smemL>>>(
        agg, deg, h0, blob(2, 0), blob(2, 1), blob(3, 0), blob(3, 1), b1, h1, M);

    // fc
    sage_gemm<64, 1, false, false><<<gemmBlocks, 256, smemF>>>(
        h1, nullptr, nullptr, blob(4, 0), blob(4, 1), nullptr, nullptr, bfc, out, M);
}

// round 6
// speedup vs baseline: 2.3795x; 1.5357x over previous
#include <cuda_runtime.h>
#include <cuda_bf16.h>
#include <stdint.h>

#define N_NODES_MAX 50048
#define E_MAX 1000000
#define FEAT 128
#define SCAN_BLK 256

__device__ __align__(256) float g_dinv[N_NODES_MAX];
__device__ __align__(256) float g_agg[N_NODES_MAX * FEAT];
__device__ __align__(256) float g_h0[N_NODES_MAX * FEAT];
__device__ __align__(256) float g_h1[N_NODES_MAX * FEAT];
__device__ int g_is64;
__device__ __align__(256) int g_degi[N_NODES_MAX];
__device__ __align__(256) int g_part[N_NODES_MAX];
__device__ __align__(256) int g_bsums[(N_NODES_MAX + SCAN_BLK - 1) / SCAN_BLK];
__device__ __align__(256) int g_offs[N_NODES_MAX + 1];
__device__ __align__(256) int g_cursor[N_NODES_MAX];
__device__ __align__(256) int g_csr[E_MAX];

// bf16 weight blobs, [n][k] row-major: [Wl0, Wr0, Wl1, Wr1, Wfc][hi/lo]
__device__ __align__(256) unsigned char g_wb[5][2][32768];

// ===========================================================================
// helpers
// ===========================================================================
__device__ __forceinline__ uint32_t smem_u32(const void* p) {
    uint32_t a;
    asm("{ .reg .u64 t; cvta.to.shared.u64 t, %1; cvt.u32.u64 %0, t; }" : "=r"(a) : "l"(p));
    return a;
}
__device__ __forceinline__ uint32_t pack_bf16x2(float x, float y) {
    __nv_bfloat162 v(__float2bfloat16(x), __float2bfloat16(y));
    return *(uint32_t*)&v;
}
__device__ __forceinline__ void ldmatrix_x4(uint32_t* r, uint32_t addr) {
    asm volatile("ldmatrix.sync.aligned.m8n8.x4.shared.b16 {%0,%1,%2,%3}, [%4];"
                 : "=r"(r[0]), "=r"(r[1]), "=r"(r[2]), "=r"(r[3]) : "r"(addr));
}
__device__ __forceinline__ void mma16816(float* d, const uint32_t* a, uint32_t b0, uint32_t b1) {
    asm volatile("mma.sync.aligned.m16n8k16.row.col.f32.bf16.bf16.f32 "
                 "{%0,%1,%2,%3}, {%4,%5,%6,%7}, {%8,%9}, {%0,%1,%2,%3};"
                 : "+f"(d[0]), "+f"(d[1]), "+f"(d[2]), "+f"(d[3])
                 : "r"(a[0]), "r"(a[1]), "r"(a[2]), "r"(a[3]), "r"(b0), "r"(b1));
}

// ===========================================================================
// edge dtype detection + CSR construction
// ===========================================================================
__global__ void detect_kernel(const int* __restrict__ ei_w, int nwords, int* __restrict__ flag) {
    if (threadIdx.x == 0 && blockIdx.x == 0) {
        int all_zero = 1;
        for (int i = 0; i < 64; i++) {
            int pos = 1 + 2 * i;
            if (pos < nwords && ei_w[pos] != 0) { all_zero = 0; break; }
        }
        *flag = all_zero;
    }
}

__device__ __forceinline__ int edge_idx(const void* ei, long long pos, int is64) {
    if (is64) return (int)((const long long*)ei)[pos];
    return ((const int*)ei)[pos];
}

__global__ void degree_kernel(const void* __restrict__ ei, int* __restrict__ degi,
                              int E, int M, const int* __restrict__ flag) {
    int e = blockIdx.x * blockDim.x + threadIdx.x;
    if (e >= E) return;
    int d = edge_idx(ei, (long long)E + e, *flag);
    if (d < 0 || d >= M) return;
    atomicAdd(&degi[d], 1);
}

__global__ void scan_blocks(const int* __restrict__ degi, int* __restrict__ part,
                            int* __restrict__ bsums, int M) {
    __shared__ int sh[SCAN_BLK];
    int i = blockIdx.x * SCAN_BLK + threadIdx.x;
    sh[threadIdx.x] = (i < M) ? degi[i] : 0;
    __syncthreads();
#pragma unroll
    for (int off = 1; off < SCAN_BLK; off <<= 1) {
        int t = (threadIdx.x >= off) ? sh[threadIdx.x - off] : 0;
        __syncthreads();
        sh[threadIdx.x] += t;
        __syncthreads();
    }
    if (i < M) part[i] = sh[threadIdx.x];
    if (threadIdx.x == SCAN_BLK - 1) bsums[blockIdx.x] = sh[SCAN_BLK - 1];
}

__global__ void scan_sums(int* __restrict__ bsums, int nb) {
    if (threadIdx.x == 0 && blockIdx.x == 0) {
        int acc = 0;
        for (int i = 0; i < nb; i++) { int v = bsums[i]; bsums[i] = acc; acc += v; }
    }
}

__global__ void scan_finalize(const int* __restrict__ part, const int* __restrict__ bsums,
                              const int* __restrict__ degi, int* __restrict__ offs,
                              int* __restrict__ cursor, float* __restrict__ dinv, int M) {
    int i = blockIdx.x * blockDim.x + threadIdx.x;
    if (i >= M) return;
    int inc = part[i] + bsums[i / SCAN_BLK];
    offs[i + 1] = inc;
    cursor[i] = inc - degi[i];
    dinv[i] = 1.0f / fmaxf((float)degi[i], 1.0f);
    if (i == 0) offs[0] = 0;
}

__global__ void csr_fill(const void* __restrict__ ei, int* __restrict__ cursor,
                         int* __restrict__ csr, int E, int M, const int* __restrict__ flag) {
    int e = blockIdx.x * blockDim.x + threadIdx.x;
    if (e >= E) return;
    int is64 = *flag;
    int s = edge_idx(ei, e, is64);
    int d = edge_idx(ei, (long long)E + e, is64);
    if (s < 0 || s >= M || d < 0 || d >= M) return;
    int slot = atomicAdd(&cursor[d], 1);
    csr[slot] = s;
}

// ===========================================================================
// gather: one warp per node; unroll-4 neighbor loads (MLP=4); writes
// agg row once, pre-scaled by dinv. No float atomics, no agg memset needed.
// ===========================================================================
__global__ void __launch_bounds__(256)
gather_kernel(const float* __restrict__ feat, const int* __restrict__ csr,
              const int* __restrict__ offs, const float* __restrict__ dinv,
              float* __restrict__ agg, int M) {
    int warp = (blockIdx.x * blockDim.x + threadIdx.x) >> 5;
    int lane = threadIdx.x & 31;
    if (warp >= M) return;
    int beg = offs[warp], end = offs[warp + 1];
    float4 acc = make_float4(0.f, 0.f, 0.f, 0.f);
    int j = beg;
    for (; j + 4 <= end; j += 4) {
        int s0 = csr[j], s1 = csr[j + 1], s2 = csr[j + 2], s3 = csr[j + 3];
        float4 v0 = *((const float4*)(feat + (size_t)s0 * FEAT) + lane);
        float4 v1 = *((const float4*)(feat + (size_t)s1 * FEAT) + lane);
        float4 v2 = *((const float4*)(feat + (size_t)s2 * FEAT) + lane);
        float4 v3 = *((const float4*)(feat + (size_t)s3 * FEAT) + lane);
        acc.x += v0.x + v1.x + v2.x + v3.x;
        acc.y += v0.y + v1.y + v2.y + v3.y;
        acc.z += v0.z + v1.z + v2.z + v3.z;
        acc.w += v0.w + v1.w + v2.w + v3.w;
    }
    for (; j < end; j++) {
        int s = csr[j];
        float4 v = *((const float4*)(feat + (size_t)s * FEAT) + lane);
        acc.x += v.x; acc.y += v.y; acc.z += v.z; acc.w += v.w;
    }
    float sc = dinv[warp];
    acc.x *= sc; acc.y *= sc; acc.z *= sc; acc.w *= sc;
    *((float4*)(agg + (size_t)warp * FEAT) + lane) = acc;
}

// ===========================================================================
// weight prep: all 5 weights in one launch (grid.y selects weight).
// Blob layout: [n][k], k fastest. W input is [K=128, N] row-major f32.
// ===========================================================================
__global__ void prep_all(const float* __restrict__ W0, const float* __restrict__ W1,
                         const float* __restrict__ W2, const float* __restrict__ W3,
                         const float* __restrict__ W4, unsigned char* __restrict__ wb) {
    int w = blockIdx.y;
    int N = (w == 4) ? 64 : 128;
    int idx = blockIdx.x * blockDim.x + threadIdx.x;
    if (idx >= N * 128) return;
    const float* W = (w == 0) ? W0 : (w == 1) ? W1 : (w == 2) ? W2 : (w == 3) ? W3 : W4;
    unsigned char* bh = wb + ((size_t)w * 2 + 0) * 32768;
    unsigned char* bl = wb + ((size_t)w * 2 + 1) * 32768;
    int n = idx >> 7, k = idx & 127;
    float wv = W[k * N + n];
    __nv_bfloat16 h = __float2bfloat16(wv);
    __nv_bfloat16 l = __float2bfloat16(wv - __bfloat162float(h));
    *(__nv_bfloat16*)(bh + n * 256 + k * 2) = h;
    *(__nv_bfloat16*)(bl + n * 256 + k * 2) = l;
}

// ===========================================================================
// HMMA GEMM: out = act( sum_ops A_op @ W_op^T + bias ), W blobs are [n][k].
// CTA tile: 128 rows x N cols, 256 threads (8 warps, 4x2 warp grid).
// Hi/lo split: 3 passes (Ah*Bh, Al*Bh, Ah*Bl) accumulated in f32 frags.
// SMEM rows padded to 272 B -> conflict-free ldmatrix.
// ===========================================================================
#define ROWB 272

template<int N, int NOPS, bool RELU>
__global__ void __launch_bounds__(256)
sage_gemm(const float* __restrict__ A0, const float* __restrict__ A1,
          const unsigned char* __restrict__ B0h, const unsigned char* __restrict__ B0l,
          const unsigned char* __restrict__ B1h, const unsigned char* __restrict__ B1l,
          const float* __restrict__ bias, float* __restrict__ out, int M) {
    extern __shared__ __align__(16) unsigned char smem[];
    constexpr int SM_AH = 0;
    constexpr int SM_AL = 128 * ROWB;
    constexpr int SM_BH = 2 * 128 * ROWB;
    constexpr int SM_BL = SM_BH + N * ROWB;
    constexpr int NP = N / 32;
    constexpr int NJ = 2 * NP;

    const int tid  = threadIdx.x;
    const int wid  = tid >> 5;
    const int lane = tid & 31;
    const int mw   = wid >> 1;
    const int nw   = wid & 1;
    const int mbase = mw * 32;
    const int nbase = nw * (N / 2);
    const int m0 = blockIdx.x * 128;
    const uint32_t sb = smem_u32(smem);

    float acc[2][NJ][4];
#pragma unroll
    for (int t = 0; t < 2; t++)
#pragma unroll
        for (int j = 0; j < NJ; j++)
#pragma unroll
            for (int q = 0; q < 4; q++) acc[t][j][q] = 0.0f;

    const uint32_t aAddrBase = sb + SM_AH + (uint32_t)(mbase + (lane & 15)) * ROWB
                             + ((lane >> 4) & 1) * 16;
    const uint32_t bRow = (uint32_t)(nbase + (lane & 7) + ((lane >> 4) & 1) * 8);
    const uint32_t bAddrBase = sb + SM_BH + bRow * ROWB + ((lane >> 3) & 1) * 16;

    for (int op = 0; op < NOPS; op++) {
        const float* A = (op == 0) ? A0 : A1;
        const unsigned char* Bh = (op == 0) ? B0h : B1h;
        const unsigned char* Bl = (op == 0) ? B0l : B1l;

        if (op > 0) __syncthreads();

        // --- A tile: f32 -> hi/lo bf16 ---
#pragma unroll
        for (int i = 0; i < 16; i++) {
            int g = tid + 256 * i;
            int r = g >> 5;
            int kb = (g & 31) << 2;
            int gr = m0 + r;
            float4 a = make_float4(0.f, 0.f, 0.f, 0.f);
            if (gr < M) a = *(const float4*)(A + (size_t)gr * FEAT + kb);
            __nv_bfloat16 hx = __float2bfloat16(a.x), hy = __float2bfloat16(a.y);
            __nv_bfloat16 hz = __float2bfloat16(a.z), hw = __float2bfloat16(a.w);
            uint2 hv, lv;
            {
                __nv_bfloat162 p0(hx, hy), p1(hz, hw);
                hv.x = *(uint32_t*)&p0; hv.y = *(uint32_t*)&p1;
            }
            lv.x = pack_bf16x2(a.x - __bfloat162float(hx), a.y - __bfloat162float(hy));
            lv.y = pack_bf16x2(a.z - __bfloat162float(hz), a.w - __bfloat162float(hw));
            uint32_t off = (uint32_t)r * ROWB + kb * 2;
            *(uint2*)(smem + SM_AH + off) = hv;
            *(uint2*)(smem + SM_AL + off) = lv;
        }
        // --- B tiles ---
#pragma unroll
        for (int i = 0; i < (N * 16) / 256; i++) {
            int g = tid + 256 * i;
            int row = g >> 4, col = g & 15;
            uint32_t off = (uint32_t)row * ROWB + col * 16;
            *(uint4*)(smem + SM_BH + off) = ((const uint4*)Bh)[g];
            *(uint4*)(smem + SM_BL + off) = ((const uint4*)Bl)[g];
        }
        __syncthreads();

#pragma unroll
        for (int pass = 0; pass < 3; pass++) {
            uint32_t aBase = aAddrBase + ((pass == 1) ? (uint32_t)(SM_AL - SM_AH) : 0u);
            uint32_t bBase = bAddrBase + ((pass == 2) ? (uint32_t)(SM_BL - SM_BH) : 0u);
#pragma unroll
            for (int ks = 0; ks < 8; ks++) {
                uint32_t kOff = ks * 32;
                uint32_t af[2][4];
                ldmatrix_x4(af[0], aBase + kOff);
                ldmatrix_x4(af[1], aBase + 16 * ROWB + kOff);
                uint32_t bf[NP][4];
#pragma unroll
                for (int p = 0; p < NP; p++)
                    ldmatrix_x4(bf[p], bBase + (uint32_t)(p * 16) * ROWB + kOff);
#pragma unroll
                for (int t = 0; t < 2; t++)
#pragma unroll
                    for (int p = 0; p < NP; p++) {
                        mma16816(acc[t][2 * p + 0], af[t], bf[p][0], bf[p][1]);
                        mma16816(acc[t][2 * p + 1], af[t], bf[p][2], bf[p][3]);
                    }
            }
        }
    }

    const int group = lane >> 2;
    const int tig   = lane & 3;
#pragma unroll
    for (int t = 0; t < 2; t++) {
#pragma unroll
        for (int j = 0; j < NJ; j++) {
            int col = nbase + j * 8 + tig * 2;
            float2 b = *(const float2*)(bias + col);
            int r0 = m0 + mbase + t * 16 + group;
            float2 o0, o1;
            o0.x = acc[t][j][0] + b.x; o0.y = acc[t][j][1] + b.y;
            o1.x = acc[t][j][2] + b.x; o1.y = acc[t][j][3] + b.y;
            if (RELU) {
                o0.x = fmaxf(o0.x, 0.f); o0.y = fmaxf(o0.y, 0.f);
                o1.x = fmaxf(o1.x, 0.f); o1.y = fmaxf(o1.y, 0.f);
            }
            if (r0 < M)     *(float2*)(out + (size_t)r0 * N + col)       = o0;
            if (r0 + 8 < M) *(float2*)(out + (size_t)(r0 + 8) * N + col) = o1;
        }
    }
}

// ===========================================================================
extern "C" void kernel_launch(void* const* d_in, const int* in_sizes, int n_in,
                              void* d_out, int out_size) {
    const float* x   = (const float*)d_in[0];
    const void*  ei  = d_in[1];
    const float* Wl0 = (const float*)d_in[2];
    const float* Wr0 = (const float*)d_in[3];
    const float* b0  = (const float*)d_in[4];
    const float* Wl1 = (const float*)d_in[5];
    const float* Wr1 = (const float*)d_in[6];
    const float* b1  = (const float*)d_in[7];
    const float* Wfc = (const float*)d_in[8];
    const float* bfc = (const float*)d_in[9];
    float*       out = (float*)d_out;

    const int M = in_sizes[0] / FEAT;   // 50000
    const int E = in_sizes[1] / 2;      // 800000

    float *dinv, *agg, *h0, *h1;
    int *flag, *degi, *part, *bsums, *offs, *cursor, *csr;
    unsigned char* wb;
    cudaGetSymbolAddress((void**)&dinv, g_dinv);
    cudaGetSymbolAddress((void**)&agg,  g_agg);
    cudaGetSymbolAddress((void**)&h0,   g_h0);
    cudaGetSymbolAddress((void**)&h1,   g_h1);
    cudaGetSymbolAddress((void**)&flag, g_is64);
    cudaGetSymbolAddress((void**)&degi, g_degi);
    cudaGetSymbolAddress((void**)&part, g_part);
    cudaGetSymbolAddress((void**)&bsums, g_bsums);
    cudaGetSymbolAddress((void**)&offs, g_offs);
    cudaGetSymbolAddress((void**)&cursor, g_cursor);
    cudaGetSymbolAddress((void**)&csr,  g_csr);
    cudaGetSymbolAddress((void**)&wb,   g_wb);
    auto blob = [&](int w, int hl) { return wb + ((size_t)w * 2 + hl) * 32768; };

    const int smemL = (2 * 128 + 2 * 128) * ROWB;   // 139264
    const int smemF = (2 * 128 + 2 * 64) * ROWB;    // 104448
    cudaFuncSetAttribute(sage_gemm<128, 2, true>,  cudaFuncAttributeMaxDynamicSharedMemorySize, smemL);
    cudaFuncSetAttribute(sage_gemm<64, 1, false>,  cudaFuncAttributeMaxDynamicSharedMemorySize, smemF);

    cudaMemsetAsync(degi, 0, (size_t)M * sizeof(int));

    detect_kernel<<<1, 32>>>((const int*)ei, 2 * E, flag);

    dim3 prepGrid(64, 5);
    prep_all<<<prepGrid, 256>>>(Wl0, Wr0, Wl1, Wr1, Wfc, wb);

    // CSR build
    const int nb = (M + SCAN_BLK - 1) / SCAN_BLK;
    degree_kernel<<<(E + 255) / 256, 256>>>(ei, degi, E, M, flag);
    scan_blocks<<<nb, SCAN_BLK>>>(degi, part, bsums, M);
    scan_sums<<<1, 32>>>(bsums, nb);
    scan_finalize<<<(M + 255) / 256, 256>>>(part, bsums, degi, offs, cursor, dinv, M);
    csr_fill<<<(E + 255) / 256, 256>>>(ei, cursor, csr, E, M, flag);

    const int gatherBlocks = (M * 32 + 255) / 256;
    const int gemmBlocks   = (M + 127) / 128;

    // layer 0
    gather_kernel<<<gatherBlocks, 256>>>(x, csr, offs, dinv, agg, M);
    sage_gemm<128, 2, true><<<gemmBlocks, 256, smemL>>>(
        agg, x, blob(0, 0), blob(0, 1), blob(1, 0), blob(1, 1), b0, h0, M);

    // layer 1
    gather_kernel<<<gatherBlocks, 256>>>(h0, csr, offs, dinv, agg, M);
    sage_gemm<128, 2, true><<<gemmBlocks, 256, smemL>>>(
        agg, h0, blob(2, 0), blob(2, 1), blob(3, 0), blob(3, 1), b1, h1, M);

    // fc
    sage_gemm<64, 1, false><<<gemmBlocks, 256, smemF>>>(
        h1, nullptr, blob(4, 0), blob(4, 1), nullptr, nullptr, bfc, out, M);
}